// round 2
// baseline (speedup 1.0000x reference)
#include <cuda_runtime.h>
#include <math.h>

#define BB 2
#define SS 2048
#define HH 3584
#define NH 28
#define NKV 4
#define HD 128
#define QSZ (NH*HD)            // 3584
#define KVSZ (NKV*HD)          // 512
#define QKVSZ (QSZ + 2*KVSZ)   // 4608
#define NT (BB*SS)             // 4096

// Scratch (no cudaMalloc allowed)
__device__ float g_qkv[(size_t)NT * QKVSZ];   // ~75.5 MB
__device__ float g_attn[(size_t)NT * QSZ];    // ~58.7 MB
__device__ float g_cos[SS * 64];
__device__ float g_sin[SS * 64];

// ---------------------------------------------------------------------------
// Packed f32x2 helpers (FFMA2 — only reachable via PTX)
// ---------------------------------------------------------------------------
__device__ __forceinline__ unsigned long long pk2(float lo, float hi) {
    unsigned long long r;
    asm("mov.b64 %0, {%1, %2};" : "=l"(r) : "f"(lo), "f"(hi));
    return r;
}
__device__ __forceinline__ void up2(unsigned long long v, float& lo, float& hi) {
    asm("mov.b64 {%0, %1}, %2;" : "=f"(lo), "=f"(hi) : "l"(v));
}
__device__ __forceinline__ unsigned long long fma2v(unsigned long long a,
                                                    unsigned long long b,
                                                    unsigned long long c) {
    unsigned long long d;
    asm("fma.rn.f32x2 %0, %1, %2, %3;" : "=l"(d) : "l"(a), "l"(b), "l"(c));
    return d;
}
__device__ __forceinline__ unsigned long long mul2v(unsigned long long a,
                                                    unsigned long long b) {
    unsigned long long d;
    asm("mul.rn.f32x2 %0, %1, %2;" : "=l"(d) : "l"(a), "l"(b));
    return d;
}

// ---------------------------------------------------------------------------
// RoPE tables, computed in fp64 for angle accuracy
// ---------------------------------------------------------------------------
__global__ void rope_table_kernel(float* __restrict__ ct, float* __restrict__ st) {
    int p = blockIdx.x;
    int d = threadIdx.x;
    double inv = exp(((double)(-2 * d) / 128.0) * log(1000000.0));
    double a = (double)p * inv;
    ct[p * 64 + d] = (float)cos(a);
    st[p * 64 + d] = (float)sin(a);
}

// ---------------------------------------------------------------------------
// In-place neox RoPE on q and k sections of g_qkv
// ---------------------------------------------------------------------------
__global__ void rope_kernel(float* __restrict__ qkv, const int* __restrict__ pos,
                            const float* __restrict__ ct, const float* __restrict__ st) {
    int t = blockIdx.x;
    int hh = blockIdx.y;
    int d = threadIdx.x;
    int p = pos[t];
    float c = ct[p * 64 + d];
    float s = st[p * 64 + d];
    float* base = qkv + (size_t)t * QKVSZ +
                  (hh < NH ? hh * HD : QSZ + (hh - NH) * HD);
    float x1 = base[d];
    float x2 = base[d + 64];
    base[d]      = x1 * c - x2 * s;
    base[d + 64] = x2 * c + x1 * s;
}

// ---------------------------------------------------------------------------
// 128x128x8 SGEMM with FFMA2 inner product. C = A @ B (+bias), row-major.
// 256 threads, 8x8 per thread (packed as 8x4 f32x2 pairs along N).
// ---------------------------------------------------------------------------
__global__ __launch_bounds__(256) void sgemm_bias(
    const float* __restrict__ A, const float* __restrict__ Bm,
    const float* __restrict__ bias, float* __restrict__ C,
    int M, int N, int K)
{
    __shared__ __align__(16) float As[8][132];
    __shared__ __align__(16) float Bs[8][132];
    int tid = threadIdx.x;
    int ty = tid >> 4, tx = tid & 15;
    int bm = blockIdx.y * 128, bn = blockIdx.x * 128;

    int arow = tid >> 1, akq = (tid & 1) << 2;
    int brow = tid >> 5, bcol = (tid & 31) << 2;

    const float* Ap = A + (size_t)(bm + arow) * K + akq;
    const float* Bp = Bm + (size_t)brow * N + bn + bcol;

    unsigned long long acc2[8][4];
#pragma unroll
    for (int i = 0; i < 8; i++)
#pragma unroll
        for (int j = 0; j < 4; j++) acc2[i][j] = 0ull;

    float4 av = *(const float4*)Ap;
    float4 bv = *(const float4*)Bp;

    for (int k0 = 0; k0 < K; k0 += 8) {
        As[akq + 0][arow] = av.x;
        As[akq + 1][arow] = av.y;
        As[akq + 2][arow] = av.z;
        As[akq + 3][arow] = av.w;
        *(float4*)&Bs[brow][bcol] = bv;
        __syncthreads();

        if (k0 + 8 < K) {
            av = *(const float4*)(Ap + k0 + 8);
            bv = *(const float4*)(Bp + (size_t)(k0 + 8) * N);
        }

#pragma unroll
        for (int kk = 0; kk < 8; kk++) {
            float a[8];
            *(float4*)(a)     = *(const float4*)&As[kk][ty * 8];
            *(float4*)(a + 4) = *(const float4*)&As[kk][ty * 8 + 4];
            ulonglong2 bl0 = *(const ulonglong2*)&Bs[kk][tx * 8];
            ulonglong2 bl1 = *(const ulonglong2*)&Bs[kk][tx * 8 + 4];
            unsigned long long b2[4] = {bl0.x, bl0.y, bl1.x, bl1.y};
#pragma unroll
            for (int i = 0; i < 8; i++) {
                unsigned long long ai = pk2(a[i], a[i]);
#pragma unroll
                for (int j = 0; j < 4; j++)
                    acc2[i][j] = fma2v(ai, b2[j], acc2[i][j]);
            }
        }
        __syncthreads();
    }

#pragma unroll
    for (int i = 0; i < 8; i++) {
        int r = bm + ty * 8 + i;
        float* Cp = C + (size_t)r * N + bn + tx * 8;
        float v[8];
#pragma unroll
        for (int j = 0; j < 4; j++) up2(acc2[i][j], v[2 * j], v[2 * j + 1]);
#pragma unroll
        for (int j = 0; j < 8; j++) {
            float o = v[j];
            if (bias) o += bias[bn + tx * 8 + j];
            Cp[j] = o;
        }
    }
}

// ---------------------------------------------------------------------------
// Flash attention: 64x64 tiles, D=128, causal, GQA. FFMA2 in QK (packed along
// d, horizontal add at end) and PV (packed along output cols).
// ---------------------------------------------------------------------------
__global__ __launch_bounds__(256, 2) void flash_kernel(
    const float* __restrict__ qkv, float* __restrict__ attn)
{
    extern __shared__ float smf[];
    float* Qs = smf;                 // [64][128]
    float* Ks = Qs + 64 * 128;       // [64][132] padded
    float* Vs = Ks + 64 * 132;       // [64][128]
    float* Ps = Vs + 64 * 128;       // [64][64]

    int qb = blockIdx.x, h = blockIdx.y, b = blockIdx.z;
    int kvh = h / (NH / NKV);
    int tid = threadIdx.x;
    int ty = tid >> 4, tx = tid & 15;
    const float scale = 0.08838834764831845f;  // 1/sqrt(128)

#pragma unroll
    for (int it = 0; it < 8; it++) {
        int idx = tid + it * 256;
        int r = idx >> 5;
        int d4 = (idx & 31) << 2;
        *(float4*)&Qs[r * 128 + d4] =
            *(const float4*)(qkv + (size_t)(b * SS + qb * 64 + r) * QKVSZ + h * HD + d4);
    }

    float m[4], l[4];
    unsigned long long o2[4][4];
#pragma unroll
    for (int i = 0; i < 4; i++) {
        m[i] = -INFINITY;
        l[i] = 0.f;
#pragma unroll
        for (int c = 0; c < 4; c++) o2[i][c] = 0ull;
    }

    for (int kb = 0; kb <= qb; kb++) {
        __syncthreads();
#pragma unroll
        for (int it = 0; it < 8; it++) {
            int idx = tid + it * 256;
            int r = idx >> 5;
            int d4 = (idx & 31) << 2;
            size_t base = (size_t)(b * SS + kb * 64 + r) * QKVSZ + QSZ + kvh * HD;
            *(float4*)&Ks[r * 132 + d4] = *(const float4*)(qkv + base + d4);
            *(float4*)&Vs[r * 128 + d4] = *(const float4*)(qkv + base + KVSZ + d4);
        }
        __syncthreads();

        unsigned long long sc2[4][4];
#pragma unroll
        for (int i = 0; i < 4; i++)
#pragma unroll
            for (int j = 0; j < 4; j++) sc2[i][j] = 0ull;

        for (int d = 0; d < HD; d += 4) {
            unsigned long long qa[4], qb2[4], ka[4], kb2[4];
#pragma unroll
            for (int i = 0; i < 4; i++) {
                ulonglong2 t = *(const ulonglong2*)&Qs[(ty + 16 * i) * 128 + d];
                qa[i] = t.x; qb2[i] = t.y;
            }
#pragma unroll
            for (int j = 0; j < 4; j++) {
                ulonglong2 t = *(const ulonglong2*)&Ks[(tx + 16 * j) * 132 + d];
                ka[j] = t.x; kb2[j] = t.y;
            }
#pragma unroll
            for (int i = 0; i < 4; i++)
#pragma unroll
                for (int j = 0; j < 4; j++) {
                    sc2[i][j] = fma2v(qa[i], ka[j], sc2[i][j]);
                    sc2[i][j] = fma2v(qb2[i], kb2[j], sc2[i][j]);
                }
        }

        bool diag = (kb == qb);
#pragma unroll
        for (int i = 0; i < 4; i++) {
            float sc[4];
#pragma unroll
            for (int j = 0; j < 4; j++) {
                float lo, hi;
                up2(sc2[i][j], lo, hi);
                sc[j] = (lo + hi) * scale;
                if (diag && (tx + 16 * j) > (ty + 16 * i)) sc[j] = -INFINITY;
            }
            float mm = fmaxf(fmaxf(sc[0], sc[1]), fmaxf(sc[2], sc[3]));
            mm = fmaxf(mm, __shfl_xor_sync(0xffffffffu, mm, 1));
            mm = fmaxf(mm, __shfl_xor_sync(0xffffffffu, mm, 2));
            mm = fmaxf(mm, __shfl_xor_sync(0xffffffffu, mm, 4));
            mm = fmaxf(mm, __shfl_xor_sync(0xffffffffu, mm, 8));
            float mnew = fmaxf(m[i], mm);
            float alpha = __expf(m[i] - mnew);
            float ps = 0.f;
#pragma unroll
            for (int j = 0; j < 4; j++) {
                float p = __expf(sc[j] - mnew);
                Ps[(ty + 16 * i) * 64 + tx + 16 * j] = p;
                ps += p;
            }
            ps += __shfl_xor_sync(0xffffffffu, ps, 1);
            ps += __shfl_xor_sync(0xffffffffu, ps, 2);
            ps += __shfl_xor_sync(0xffffffffu, ps, 4);
            ps += __shfl_xor_sync(0xffffffffu, ps, 8);
            l[i] = l[i] * alpha + ps;
            m[i] = mnew;
            unsigned long long a2 = pk2(alpha, alpha);
#pragma unroll
            for (int c = 0; c < 4; c++) o2[i][c] = mul2v(o2[i][c], a2);
        }
        __syncthreads();

#pragma unroll 4
        for (int kc = 0; kc < 64; kc++) {
            ulonglong2 v0 = *(const ulonglong2*)&Vs[kc * 128 + tx * 8];
            ulonglong2 v1 = *(const ulonglong2*)&Vs[kc * 128 + tx * 8 + 4];
#pragma unroll
            for (int i = 0; i < 4; i++) {
                float p = Ps[(ty + 16 * i) * 64 + kc];
                unsigned long long p2 = pk2(p, p);
                o2[i][0] = fma2v(p2, v0.x, o2[i][0]);
                o2[i][1] = fma2v(p2, v0.y, o2[i][1]);
                o2[i][2] = fma2v(p2, v1.x, o2[i][2]);
                o2[i][3] = fma2v(p2, v1.y, o2[i][3]);
            }
        }
    }

#pragma unroll
    for (int i = 0; i < 4; i++) {
        float inv = 1.0f / l[i];
        int t = b * SS + qb * 64 + ty + 16 * i;
        float* dst = attn + (size_t)t * QSZ + h * HD + tx * 8;
        float v[8];
#pragma unroll
        for (int c = 0; c < 4; c++) up2(o2[i][c], v[2 * c], v[2 * c + 1]);
#pragma unroll
        for (int c = 0; c < 8; c++) dst[c] = v[c] * inv;
    }
}

// ---------------------------------------------------------------------------
extern "C" void kernel_launch(void* const* d_in, const int* in_sizes, int n_in,
                              void* d_out, int out_size)
{
    (void)in_sizes; (void)n_in; (void)out_size;
    const float* hidden    = (const float*)d_in[0];
    const int*   positions = (const int*)d_in[1];
    const float* Wqkv      = (const float*)d_in[2];
    const float* bqkv      = (const float*)d_in[3];
    const float* Wo        = (const float*)d_in[4];
    float* out = (float*)d_out;

    float *qkv, *attn, *ct, *st;
    cudaGetSymbolAddress((void**)&qkv,  g_qkv);
    cudaGetSymbolAddress((void**)&attn, g_attn);
    cudaGetSymbolAddress((void**)&ct,   g_cos);
    cudaGetSymbolAddress((void**)&st,   g_sin);

    const int flash_smem = (64 * 128 + 64 * 132 + 64 * 128 + 64 * 64) * 4; // 115712
    cudaFuncSetAttribute(flash_kernel,
                         cudaFuncAttributeMaxDynamicSharedMemorySize, flash_smem);

    rope_table_kernel<<<SS, 64>>>(ct, st);

    dim3 g1(QKVSZ / 128, NT / 128);
    sgemm_bias<<<g1, 256>>>(hidden, Wqkv, bqkv, qkv, NT, QKVSZ, HH);

    dim3 gr(NT, NH + NKV);
    rope_kernel<<<gr, 64>>>(qkv, positions, ct, st);

    dim3 gf(SS / 64, NH, BB);
    flash_kernel<<<gf, 256, flash_smem>>>(qkv, attn);

    dim3 g2(HH / 128, NT / 128);
    sgemm_bias<<<g2, 256>>>(attn, Wo, nullptr, out, NT, HH, HH);
}

// round 4
// speedup vs baseline: 1.8515x; 1.8515x over previous
#include <cuda_runtime.h>
#include <math.h>

#define BB 2
#define SS 2048
#define HH 3584
#define NH 28
#define NKV 4
#define HD 128
#define QSZ (NH*HD)            // 3584
#define KVSZ (NKV*HD)          // 512
#define QKVSZ (QSZ + 2*KVSZ)   // 4608
#define NT (BB*SS)             // 4096

// Scratch (no cudaMalloc allowed)
__device__ float g_qkv[(size_t)NT * QKVSZ];   // ~75.5 MB
__device__ float g_attn[(size_t)NT * QSZ];    // ~58.7 MB
__device__ float g_cos[SS * 64];
__device__ float g_sin[SS * 64];

// ---------------------------------------------------------------------------
__device__ __forceinline__ unsigned tf32_of(float x) {
    unsigned u;
    asm("cvt.rna.tf32.f32 %0, %1;" : "=r"(u) : "f"(x));
    return u;
}

// ---------------------------------------------------------------------------
// RoPE tables (fp64 angles)
// ---------------------------------------------------------------------------
__global__ void rope_table_kernel(float* __restrict__ ct, float* __restrict__ st) {
    int p = blockIdx.x;
    int d = threadIdx.x;
    double inv = exp(((double)(-2 * d) / 128.0) * log(1000000.0));
    double a = (double)p * inv;
    ct[p * 64 + d] = (float)cos(a);
    st[p * 64 + d] = (float)sin(a);
}

// ---------------------------------------------------------------------------
// In-place neox RoPE on q and k sections of g_qkv
// ---------------------------------------------------------------------------
__global__ void rope_kernel(float* __restrict__ qkv, const int* __restrict__ pos,
                            const float* __restrict__ ct, const float* __restrict__ st) {
    int t = blockIdx.x;
    int hh = blockIdx.y;
    int d = threadIdx.x;
    int p = pos[t];
    float c = ct[p * 64 + d];
    float s = st[p * 64 + d];
    float* base = qkv + (size_t)t * QKVSZ +
                  (hh < NH ? hh * HD : QSZ + (hh - NH) * HD);
    float x1 = base[d];
    float x2 = base[d + 64];
    base[d]      = x1 * c - x2 * s;
    base[d + 64] = x2 * c + x1 * s;
}

// ---------------------------------------------------------------------------
// tf32 tensor-core GEMM: C[MxN] = A[MxK] @ B[KxN] (+bias), row-major.
// Block tile 128x128x16, 256 threads (8 warps, 4x2), warp tile 32x64,
// mma.sync.aligned.m16n8k8 tf32. A/B converted to tf32 (rna) on smem store.
//   As: [128 m][stride 20]  (16 k + pad)  -> conflict-free a-frag LDS
//   Bs: [16 k][stride 136]  (128 n + pad) -> conflict-free b-frag LDS
// ---------------------------------------------------------------------------
__global__ __launch_bounds__(256) void sgemm_tf32(
    const float* __restrict__ A, const float* __restrict__ Bm,
    const float* __restrict__ bias, float* __restrict__ C,
    int M, int N, int K)
{
    __shared__ __align__(16) unsigned As[128 * 20];
    __shared__ __align__(16) unsigned Bs[16 * 136];

    int tid = threadIdx.x;
    int lane = tid & 31;
    int wid = tid >> 5;
    int warp_m = wid >> 1;      // 0..3  -> 32 rows each
    int warp_n = wid & 1;       // 0..1  -> 64 cols each
    int g4 = lane >> 2;         // groupID 0..7
    int t4 = lane & 3;          // threadID_in_group 0..3

    int bm = blockIdx.y * 128, bn = blockIdx.x * 128;

    // Global load mapping:
    //   A tile 128x16 = 512 float4 chunks; thread handles ids {tid, tid+256}
    //     row = id>>2, kc = (id&3)*4
    //   B tile 16x128 = 512 float4 chunks; ids {tid, tid+256}
    //     kr = id>>5, col = (id&31)*4
    int a_r0 = tid >> 2,          a_c0 = (tid & 3) << 2;
    int a_r1 = (tid + 256) >> 2,  a_c1 = a_c0;           // (id&3) identical
    int b_k0 = tid >> 5,          b_c0 = (tid & 31) << 2;
    int b_k1 = (tid + 256) >> 5,  b_c1 = b_c0;

    const float* Ap0 = A + (size_t)(bm + a_r0) * K + a_c0;
    const float* Ap1 = A + (size_t)(bm + a_r1) * K + a_c1;
    const float* Bp0 = Bm + (size_t)b_k0 * N + bn + b_c0;
    const float* Bp1 = Bm + (size_t)b_k1 * N + bn + b_c1;

    float acc[2][8][4];
#pragma unroll
    for (int i = 0; i < 2; i++)
#pragma unroll
        for (int j = 0; j < 8; j++)
#pragma unroll
            for (int c = 0; c < 4; c++) acc[i][j][c] = 0.f;

    float4 av0 = *(const float4*)Ap0;
    float4 av1 = *(const float4*)Ap1;
    float4 bv0 = *(const float4*)Bp0;
    float4 bv1 = *(const float4*)Bp1;

    for (int k0 = 0; k0 < K; k0 += 16) {
        // store current tile to smem (tf32-converted)
        As[a_r0 * 20 + a_c0 + 0] = tf32_of(av0.x);
        As[a_r0 * 20 + a_c0 + 1] = tf32_of(av0.y);
        As[a_r0 * 20 + a_c0 + 2] = tf32_of(av0.z);
        As[a_r0 * 20 + a_c0 + 3] = tf32_of(av0.w);
        As[a_r1 * 20 + a_c1 + 0] = tf32_of(av1.x);
        As[a_r1 * 20 + a_c1 + 1] = tf32_of(av1.y);
        As[a_r1 * 20 + a_c1 + 2] = tf32_of(av1.z);
        As[a_r1 * 20 + a_c1 + 3] = tf32_of(av1.w);
        {
            uint4 u0 = make_uint4(tf32_of(bv0.x), tf32_of(bv0.y), tf32_of(bv0.z), tf32_of(bv0.w));
            uint4 u1 = make_uint4(tf32_of(bv1.x), tf32_of(bv1.y), tf32_of(bv1.z), tf32_of(bv1.w));
            *(uint4*)&Bs[b_k0 * 136 + b_c0] = u0;
            *(uint4*)&Bs[b_k1 * 136 + b_c1] = u1;
        }
        __syncthreads();

        if (k0 + 16 < K) {
            av0 = *(const float4*)(Ap0 + k0 + 16);
            av1 = *(const float4*)(Ap1 + k0 + 16);
            bv0 = *(const float4*)(Bp0 + (size_t)(k0 + 16) * N);
            bv1 = *(const float4*)(Bp1 + (size_t)(k0 + 16) * N);
        }

#pragma unroll
        for (int ks = 0; ks < 16; ks += 8) {
            unsigned a[2][4], b[8][2];
#pragma unroll
            for (int mt = 0; mt < 2; mt++) {
                int m = warp_m * 32 + mt * 16 + g4;
                int col = ks + t4;
                a[mt][0] = As[m * 20 + col];
                a[mt][1] = As[(m + 8) * 20 + col];
                a[mt][2] = As[m * 20 + col + 4];
                a[mt][3] = As[(m + 8) * 20 + col + 4];
            }
#pragma unroll
            for (int nt = 0; nt < 8; nt++) {
                int n = warp_n * 64 + nt * 8 + g4;
                int row = ks + t4;
                b[nt][0] = Bs[row * 136 + n];
                b[nt][1] = Bs[(row + 4) * 136 + n];
            }
#pragma unroll
            for (int mt = 0; mt < 2; mt++)
#pragma unroll
                for (int nt = 0; nt < 8; nt++) {
                    asm volatile(
                        "mma.sync.aligned.m16n8k8.row.col.f32.tf32.tf32.f32 "
                        "{%0,%1,%2,%3}, {%4,%5,%6,%7}, {%8,%9}, {%0,%1,%2,%3};"
                        : "+f"(acc[mt][nt][0]), "+f"(acc[mt][nt][1]),
                          "+f"(acc[mt][nt][2]), "+f"(acc[mt][nt][3])
                        : "r"(a[mt][0]), "r"(a[mt][1]), "r"(a[mt][2]), "r"(a[mt][3]),
                          "r"(b[nt][0]), "r"(b[nt][1]));
                }
        }
        __syncthreads();
    }

    // epilogue
#pragma unroll
    for (int mt = 0; mt < 2; mt++) {
        int r0 = bm + warp_m * 32 + mt * 16 + g4;
#pragma unroll
        for (int nt = 0; nt < 8; nt++) {
            int c = bn + warp_n * 64 + nt * 8 + t4 * 2;
            float b0 = 0.f, b1 = 0.f;
            if (bias) { b0 = bias[c]; b1 = bias[c + 1]; }
            C[(size_t)r0 * N + c]           = acc[mt][nt][0] + b0;
            C[(size_t)r0 * N + c + 1]       = acc[mt][nt][1] + b1;
            C[(size_t)(r0 + 8) * N + c]     = acc[mt][nt][2] + b0;
            C[(size_t)(r0 + 8) * N + c + 1] = acc[mt][nt][3] + b1;
        }
    }
}

// ---------------------------------------------------------------------------
// Flash attention (round-1 scalar version): 64x64 tiles, D=128, causal, GQA.
// ---------------------------------------------------------------------------
__global__ __launch_bounds__(256) void flash_kernel(
    const float* __restrict__ qkv, float* __restrict__ attn)
{
    extern __shared__ float smf[];
    float* Qs = smf;                 // [64][128]
    float* Ks = Qs + 64 * 128;       // [64][132] padded
    float* Vs = Ks + 64 * 132;       // [64][128]
    float* Ps = Vs + 64 * 128;       // [64][64]

    int qb = blockIdx.x, h = blockIdx.y, b = blockIdx.z;
    int kvh = h / (NH / NKV);
    int tid = threadIdx.x;
    int ty = tid >> 4, tx = tid & 15;
    const float scale = 0.08838834764831845f;  // 1/sqrt(128)

#pragma unroll
    for (int it = 0; it < 8; it++) {
        int idx = tid + it * 256;
        int r = idx >> 5;
        int d4 = (idx & 31) << 2;
        *(float4*)&Qs[r * 128 + d4] =
            *(const float4*)(qkv + (size_t)(b * SS + qb * 64 + r) * QKVSZ + h * HD + d4);
    }

    float m[4], l[4], o[4][8];
#pragma unroll
    for (int i = 0; i < 4; i++) {
        m[i] = -INFINITY;
        l[i] = 0.f;
#pragma unroll
        for (int c = 0; c < 8; c++) o[i][c] = 0.f;
    }

    for (int kb = 0; kb <= qb; kb++) {
        __syncthreads();
#pragma unroll
        for (int it = 0; it < 8; it++) {
            int idx = tid + it * 256;
            int r = idx >> 5;
            int d4 = (idx & 31) << 2;
            size_t base = (size_t)(b * SS + kb * 64 + r) * QKVSZ + QSZ + kvh * HD;
            *(float4*)&Ks[r * 132 + d4] = *(const float4*)(qkv + base + d4);
            *(float4*)&Vs[r * 128 + d4] = *(const float4*)(qkv + base + KVSZ + d4);
        }
        __syncthreads();

        float sc[4][4];
#pragma unroll
        for (int i = 0; i < 4; i++)
#pragma unroll
            for (int j = 0; j < 4; j++) sc[i][j] = 0.f;

        for (int d = 0; d < HD; d += 4) {
            float4 q[4], k[4];
#pragma unroll
            for (int i = 0; i < 4; i++)
                q[i] = *(const float4*)&Qs[(ty + 16 * i) * 128 + d];
#pragma unroll
            for (int j = 0; j < 4; j++)
                k[j] = *(const float4*)&Ks[(tx + 16 * j) * 132 + d];
#pragma unroll
            for (int i = 0; i < 4; i++)
#pragma unroll
                for (int j = 0; j < 4; j++) {
                    sc[i][j] = fmaf(q[i].x, k[j].x, sc[i][j]);
                    sc[i][j] = fmaf(q[i].y, k[j].y, sc[i][j]);
                    sc[i][j] = fmaf(q[i].z, k[j].z, sc[i][j]);
                    sc[i][j] = fmaf(q[i].w, k[j].w, sc[i][j]);
                }
        }

        bool diag = (kb == qb);
#pragma unroll
        for (int i = 0; i < 4; i++) {
#pragma unroll
            for (int j = 0; j < 4; j++) {
                sc[i][j] *= scale;
                if (diag && (tx + 16 * j) > (ty + 16 * i)) sc[i][j] = -INFINITY;
            }
            float mm = fmaxf(fmaxf(sc[i][0], sc[i][1]), fmaxf(sc[i][2], sc[i][3]));
            mm = fmaxf(mm, __shfl_xor_sync(0xffffffffu, mm, 1));
            mm = fmaxf(mm, __shfl_xor_sync(0xffffffffu, mm, 2));
            mm = fmaxf(mm, __shfl_xor_sync(0xffffffffu, mm, 4));
            mm = fmaxf(mm, __shfl_xor_sync(0xffffffffu, mm, 8));
            float mnew = fmaxf(m[i], mm);
            float alpha = expf(m[i] - mnew);
            float ps = 0.f;
#pragma unroll
            for (int j = 0; j < 4; j++) {
                float p = expf(sc[i][j] - mnew);
                Ps[(ty + 16 * i) * 64 + tx + 16 * j] = p;
                ps += p;
            }
            ps += __shfl_xor_sync(0xffffffffu, ps, 1);
            ps += __shfl_xor_sync(0xffffffffu, ps, 2);
            ps += __shfl_xor_sync(0xffffffffu, ps, 4);
            ps += __shfl_xor_sync(0xffffffffu, ps, 8);
            l[i] = l[i] * alpha + ps;
            m[i] = mnew;
#pragma unroll
            for (int c = 0; c < 8; c++) o[i][c] *= alpha;
        }
        __syncthreads();

#pragma unroll 4
        for (int kc = 0; kc < 64; kc++) {
            float4 v0 = *(const float4*)&Vs[kc * 128 + tx * 8];
            float4 v1 = *(const float4*)&Vs[kc * 128 + tx * 8 + 4];
#pragma unroll
            for (int i = 0; i < 4; i++) {
                float p = Ps[(ty + 16 * i) * 64 + kc];
                o[i][0] = fmaf(p, v0.x, o[i][0]);
                o[i][1] = fmaf(p, v0.y, o[i][1]);
                o[i][2] = fmaf(p, v0.z, o[i][2]);
                o[i][3] = fmaf(p, v0.w, o[i][3]);
                o[i][4] = fmaf(p, v1.x, o[i][4]);
                o[i][5] = fmaf(p, v1.y, o[i][5]);
                o[i][6] = fmaf(p, v1.z, o[i][6]);
                o[i][7] = fmaf(p, v1.w, o[i][7]);
            }
        }
    }

#pragma unroll
    for (int i = 0; i < 4; i++) {
        float inv = 1.0f / l[i];
        int t = b * SS + qb * 64 + ty + 16 * i;
        float* dst = attn + (size_t)t * QSZ + h * HD + tx * 8;
#pragma unroll
        for (int c = 0; c < 8; c++) dst[c] = o[i][c] * inv;
    }
}

// ---------------------------------------------------------------------------
extern "C" void kernel_launch(void* const* d_in, const int* in_sizes, int n_in,
                              void* d_out, int out_size)
{
    (void)in_sizes; (void)n_in; (void)out_size;
    const float* hidden    = (const float*)d_in[0];
    const int*   positions = (const int*)d_in[1];
    const float* Wqkv      = (const float*)d_in[2];
    const float* bqkv      = (const float*)d_in[3];
    const float* Wo        = (const float*)d_in[4];
    float* out = (float*)d_out;

    float *qkv, *attn, *ct, *st;
    cudaGetSymbolAddress((void**)&qkv,  g_qkv);
    cudaGetSymbolAddress((void**)&attn, g_attn);
    cudaGetSymbolAddress((void**)&ct,   g_cos);
    cudaGetSymbolAddress((void**)&st,   g_sin);

    const int flash_smem = (64 * 128 + 64 * 132 + 64 * 128 + 64 * 64) * 4; // 115712
    cudaFuncSetAttribute(flash_kernel,
                         cudaFuncAttributeMaxDynamicSharedMemorySize, flash_smem);

    rope_table_kernel<<<SS, 64>>>(ct, st);

    dim3 g1(QKVSZ / 128, NT / 128);  // (36, 32)
    sgemm_tf32<<<g1, 256>>>(hidden, Wqkv, bqkv, qkv, NT, QKVSZ, HH);

    dim3 gr(NT, NH + NKV);
    rope_kernel<<<gr, 64>>>(qkv, positions, ct, st);

    dim3 gf(SS / 64, NH, BB);
    flash_kernel<<<gf, 256, flash_smem>>>(qkv, attn);

    dim3 g2(HH / 128, NT / 128);  // (28, 32)
    sgemm_tf32<<<g2, 256>>>(attn, Wo, nullptr, out, NT, HH, HH);
}

// round 5
// speedup vs baseline: 2.9699x; 1.6040x over previous
#include <cuda_runtime.h>
#include <cuda_bf16.h>
#include <math.h>

#define BB 2
#define SS 2048
#define HH 3584
#define NH 28
#define NKV 4
#define HD 128
#define QSZ (NH*HD)            // 3584
#define KVSZ (NKV*HD)          // 512
#define QKVSZ (QSZ + 2*KVSZ)   // 4608
#define NT (BB*SS)             // 4096

// Scratch (no cudaMalloc allowed)
__device__ float g_qkv[(size_t)NT * QKVSZ];   // ~75.5 MB
__device__ float g_attn[(size_t)NT * QSZ];    // ~58.7 MB
__device__ float g_cos[SS * 64];
__device__ float g_sin[SS * 64];

// ---------------------------------------------------------------------------
__device__ __forceinline__ unsigned tf32_of(float x) {
    unsigned u;
    asm("cvt.rna.tf32.f32 %0, %1;" : "=r"(u) : "f"(x));
    return u;
}

__device__ __forceinline__ void mma_bf16(float* c, const unsigned* a,
                                         unsigned b0, unsigned b1) {
    asm volatile(
        "mma.sync.aligned.m16n8k16.row.col.f32.bf16.bf16.f32 "
        "{%0,%1,%2,%3}, {%4,%5,%6,%7}, {%8,%9}, {%0,%1,%2,%3};"
        : "+f"(c[0]), "+f"(c[1]), "+f"(c[2]), "+f"(c[3])
        : "r"(a[0]), "r"(a[1]), "r"(a[2]), "r"(a[3]), "r"(b0), "r"(b1));
}

__device__ __forceinline__ void mma_tf32(float* c,
                                         unsigned a0, unsigned a1,
                                         unsigned a2, unsigned a3,
                                         unsigned b0, unsigned b1) {
    asm volatile(
        "mma.sync.aligned.m16n8k8.row.col.f32.tf32.tf32.f32 "
        "{%0,%1,%2,%3}, {%4,%5,%6,%7}, {%8,%9}, {%0,%1,%2,%3};"
        : "+f"(c[0]), "+f"(c[1]), "+f"(c[2]), "+f"(c[3])
        : "r"(a0), "r"(a1), "r"(a2), "r"(a3), "r"(b0), "r"(b1));
}

// Split fp32 pair into packed bf16 hi-plane and lo-plane (residual) values.
__device__ __forceinline__ void split2(float x0, float x1,
                                       unsigned& hi, unsigned& lo) {
    __nv_bfloat16 h0 = __float2bfloat16_rn(x0);
    __nv_bfloat16 h1 = __float2bfloat16_rn(x1);
    float r0 = x0 - __bfloat162float(h0);
    float r1 = x1 - __bfloat162float(h1);
    __nv_bfloat162 hp; hp.x = h0; hp.y = h1;
    __nv_bfloat162 lp; lp.x = __float2bfloat16_rn(r0); lp.y = __float2bfloat16_rn(r1);
    hi = *(unsigned*)&hp;
    lo = *(unsigned*)&lp;
}

// ---------------------------------------------------------------------------
// RoPE tables (fp64 angles)
// ---------------------------------------------------------------------------
__global__ void rope_table_kernel(float* __restrict__ ct, float* __restrict__ st) {
    int p = blockIdx.x;
    int d = threadIdx.x;
    double inv = exp(((double)(-2 * d) / 128.0) * log(1000000.0));
    double a = (double)p * inv;
    ct[p * 64 + d] = (float)cos(a);
    st[p * 64 + d] = (float)sin(a);
}

// ---------------------------------------------------------------------------
// In-place neox RoPE on q and k sections of g_qkv
// ---------------------------------------------------------------------------
__global__ void rope_kernel(float* __restrict__ qkv, const int* __restrict__ pos,
                            const float* __restrict__ ct, const float* __restrict__ st) {
    int t = blockIdx.x;
    int hh = blockIdx.y;
    int d = threadIdx.x;
    int p = pos[t];
    float c = ct[p * 64 + d];
    float s = st[p * 64 + d];
    float* base = qkv + (size_t)t * QKVSZ +
                  (hh < NH ? hh * HD : QSZ + (hh - NH) * HD);
    float x1 = base[d];
    float x2 = base[d + 64];
    base[d]      = x1 * c - x2 * s;
    base[d + 64] = x2 * c + x1 * s;
}

// ---------------------------------------------------------------------------
// tf32 tensor-core GEMM (round-4, unchanged): C = A @ B (+bias), row-major.
// ---------------------------------------------------------------------------
__global__ __launch_bounds__(256) void sgemm_tf32(
    const float* __restrict__ A, const float* __restrict__ Bm,
    const float* __restrict__ bias, float* __restrict__ C,
    int M, int N, int K)
{
    __shared__ __align__(16) unsigned As[128 * 20];
    __shared__ __align__(16) unsigned Bs[16 * 136];

    int tid = threadIdx.x;
    int lane = tid & 31;
    int wid = tid >> 5;
    int warp_m = wid >> 1;
    int warp_n = wid & 1;
    int g4 = lane >> 2;
    int t4 = lane & 3;

    int bm = blockIdx.y * 128, bn = blockIdx.x * 128;

    int a_r0 = tid >> 2,          a_c0 = (tid & 3) << 2;
    int a_r1 = (tid + 256) >> 2,  a_c1 = a_c0;
    int b_k0 = tid >> 5,          b_c0 = (tid & 31) << 2;
    int b_k1 = (tid + 256) >> 5,  b_c1 = b_c0;

    const float* Ap0 = A + (size_t)(bm + a_r0) * K + a_c0;
    const float* Ap1 = A + (size_t)(bm + a_r1) * K + a_c1;
    const float* Bp0 = Bm + (size_t)b_k0 * N + bn + b_c0;
    const float* Bp1 = Bm + (size_t)b_k1 * N + bn + b_c1;

    float acc[2][8][4];
#pragma unroll
    for (int i = 0; i < 2; i++)
#pragma unroll
        for (int j = 0; j < 8; j++)
#pragma unroll
            for (int c = 0; c < 4; c++) acc[i][j][c] = 0.f;

    float4 av0 = *(const float4*)Ap0;
    float4 av1 = *(const float4*)Ap1;
    float4 bv0 = *(const float4*)Bp0;
    float4 bv1 = *(const float4*)Bp1;

    for (int k0 = 0; k0 < K; k0 += 16) {
        As[a_r0 * 20 + a_c0 + 0] = tf32_of(av0.x);
        As[a_r0 * 20 + a_c0 + 1] = tf32_of(av0.y);
        As[a_r0 * 20 + a_c0 + 2] = tf32_of(av0.z);
        As[a_r0 * 20 + a_c0 + 3] = tf32_of(av0.w);
        As[a_r1 * 20 + a_c1 + 0] = tf32_of(av1.x);
        As[a_r1 * 20 + a_c1 + 1] = tf32_of(av1.y);
        As[a_r1 * 20 + a_c1 + 2] = tf32_of(av1.z);
        As[a_r1 * 20 + a_c1 + 3] = tf32_of(av1.w);
        {
            uint4 u0 = make_uint4(tf32_of(bv0.x), tf32_of(bv0.y), tf32_of(bv0.z), tf32_of(bv0.w));
            uint4 u1 = make_uint4(tf32_of(bv1.x), tf32_of(bv1.y), tf32_of(bv1.z), tf32_of(bv1.w));
            *(uint4*)&Bs[b_k0 * 136 + b_c0] = u0;
            *(uint4*)&Bs[b_k1 * 136 + b_c1] = u1;
        }
        __syncthreads();

        if (k0 + 16 < K) {
            av0 = *(const float4*)(Ap0 + k0 + 16);
            av1 = *(const float4*)(Ap1 + k0 + 16);
            bv0 = *(const float4*)(Bp0 + (size_t)(k0 + 16) * N);
            bv1 = *(const float4*)(Bp1 + (size_t)(k0 + 16) * N);
        }

#pragma unroll
        for (int ks = 0; ks < 16; ks += 8) {
            unsigned a[2][4], b[8][2];
#pragma unroll
            for (int mt = 0; mt < 2; mt++) {
                int m = warp_m * 32 + mt * 16 + g4;
                int col = ks + t4;
                a[mt][0] = As[m * 20 + col];
                a[mt][1] = As[(m + 8) * 20 + col];
                a[mt][2] = As[m * 20 + col + 4];
                a[mt][3] = As[(m + 8) * 20 + col + 4];
            }
#pragma unroll
            for (int nt = 0; nt < 8; nt++) {
                int n = warp_n * 64 + nt * 8 + g4;
                int row = ks + t4;
                b[nt][0] = Bs[row * 136 + n];
                b[nt][1] = Bs[(row + 4) * 136 + n];
            }
#pragma unroll
            for (int mt = 0; mt < 2; mt++)
#pragma unroll
                for (int nt = 0; nt < 8; nt++)
                    mma_tf32(acc[mt][nt], a[mt][0], a[mt][1], a[mt][2], a[mt][3],
                             b[nt][0], b[nt][1]);
        }
        __syncthreads();
    }

#pragma unroll
    for (int mt = 0; mt < 2; mt++) {
        int r0 = bm + warp_m * 32 + mt * 16 + g4;
#pragma unroll
        for (int nt = 0; nt < 8; nt++) {
            int c = bn + warp_n * 64 + nt * 8 + t4 * 2;
            float b0 = 0.f, b1 = 0.f;
            if (bias) { b0 = bias[c]; b1 = bias[c + 1]; }
            C[(size_t)r0 * N + c]           = acc[mt][nt][0] + b0;
            C[(size_t)r0 * N + c + 1]       = acc[mt][nt][1] + b1;
            C[(size_t)(r0 + 8) * N + c]     = acc[mt][nt][2] + b0;
            C[(size_t)(r0 + 8) * N + c + 1] = acc[mt][nt][3] + b1;
        }
    }
}

// ---------------------------------------------------------------------------
// Tensor-core flash attention.
// Br=128 queries/CTA, Bc=64 keys/tile. 8 warps; warp w owns rows 16w..16w+15.
// QK^T: 3-pass split-bf16 (near-fp32 scores). PV: 1-pass tf32.
// Q a-frags cached in registers across all KV tiles.
// smem layout (bytes):
//   Khi bf16[64][136] @ 0       (17408)
//   Klo bf16[64][136] @ 17408   (17408)
//   Vs  f32 [64][136] @ 34816   (34816)   (tf32-rounded values)
//   Ps  f32 [128][72] @ 69632   (36864)   (tf32-rounded probs)
//   total 106496.  Qstage f32[128][132] (67584) aliases the front.
// ---------------------------------------------------------------------------
#define FL_SMEM 106496

__global__ __launch_bounds__(256, 1) void flash_mma(
    const float* __restrict__ qkv, float* __restrict__ attn)
{
    extern __shared__ char sm_raw[];
    float* Qstage = (float*)sm_raw;                          // [128][132]
    __nv_bfloat16* Khi = (__nv_bfloat16*)sm_raw;             // [64][136]
    __nv_bfloat16* Klo = (__nv_bfloat16*)(sm_raw + 17408);   // [64][136]
    float* Vs = (float*)(sm_raw + 34816);                    // [64][136]
    float* Ps = (float*)(sm_raw + 69632);                    // [128][72]

    int qb = blockIdx.x, h = blockIdx.y, b = blockIdx.z;
    int kvh = h / (NH / NKV);
    int tid = threadIdx.x;
    int lane = tid & 31;
    int wid = tid >> 5;
    int g4 = lane >> 2;
    int t4 = lane & 3;
    int wrow = wid * 16;
    const float scale = 0.08838834764831845f;  // 1/sqrt(128)

    // ---- stage Q (pre-scaled) ----
#pragma unroll
    for (int it = 0; it < 16; it++) {
        int idx = tid + it * 256;
        int r = idx >> 5;
        int d4 = (idx & 31) << 2;
        float4 v = *(const float4*)(qkv + (size_t)(b * SS + qb * 128 + r) * QKVSZ
                                    + h * HD + d4);
        v.x *= scale; v.y *= scale; v.z *= scale; v.w *= scale;
        *(float4*)&Qstage[r * 132 + d4] = v;
    }
    __syncthreads();

    // ---- extract Q a-frags (bf16 hi/lo), cached in registers ----
    unsigned qhi[8][4], qlo[8][4];
#pragma unroll
    for (int s = 0; s < 8; s++) {
        int r0 = wrow + g4;
        int c0 = 16 * s + 2 * t4;
        float2 x00 = *(float2*)&Qstage[r0 * 132 + c0];
        float2 x10 = *(float2*)&Qstage[(r0 + 8) * 132 + c0];
        float2 x01 = *(float2*)&Qstage[r0 * 132 + c0 + 8];
        float2 x11 = *(float2*)&Qstage[(r0 + 8) * 132 + c0 + 8];
        split2(x00.x, x00.y, qhi[s][0], qlo[s][0]);
        split2(x10.x, x10.y, qhi[s][1], qlo[s][1]);
        split2(x01.x, x01.y, qhi[s][2], qlo[s][2]);
        split2(x11.x, x11.y, qhi[s][3], qlo[s][3]);
    }
    __syncthreads();   // done with Qstage; region reused for K/V

    float m0 = -INFINITY, m1 = -INFINITY, l0 = 0.f, l1 = 0.f;
    float o[16][4];
#pragma unroll
    for (int nf = 0; nf < 16; nf++)
#pragma unroll
        for (int c = 0; c < 4; c++) o[nf][c] = 0.f;

    int rowg0 = qb * 128 + wrow + g4;
    int rowg1 = rowg0 + 8;
    int kbmax = 2 * qb + 1;

    for (int kb = 0; kb <= kbmax; kb++) {
        // ---- load K (split bf16) and V (tf32) tiles ----
#pragma unroll
        for (int it = 0; it < 8; it++) {
            int idx = tid + it * 256;
            int r = idx >> 5;
            int d4 = (idx & 31) << 2;
            const float* base = qkv + (size_t)(b * SS + kb * 64 + r) * QKVSZ
                                + QSZ + kvh * HD;
            float4 kf = *(const float4*)(base + d4);
            unsigned kh0, kl0, kh1, kl1;
            split2(kf.x, kf.y, kh0, kl0);
            split2(kf.z, kf.w, kh1, kl1);
            *(unsigned*)&Khi[r * 136 + d4]     = kh0;
            *(unsigned*)&Khi[r * 136 + d4 + 2] = kh1;
            *(unsigned*)&Klo[r * 136 + d4]     = kl0;
            *(unsigned*)&Klo[r * 136 + d4 + 2] = kl1;
            float4 vf = *(const float4*)(base + KVSZ + d4);
            float4 vt;
            vt.x = __uint_as_float(tf32_of(vf.x));
            vt.y = __uint_as_float(tf32_of(vf.y));
            vt.z = __uint_as_float(tf32_of(vf.z));
            vt.w = __uint_as_float(tf32_of(vf.w));
            *(float4*)&Vs[r * 136 + d4] = vt;
        }
        __syncthreads();

        // ---- S = Q K^T  (3-pass split-bf16) ----
        float sacc[8][4];
#pragma unroll
        for (int nf = 0; nf < 8; nf++) {
#pragma unroll
            for (int c = 0; c < 4; c++) sacc[nf][c] = 0.f;
            int key = nf * 8 + g4;
#pragma unroll
            for (int s = 0; s < 8; s++) {
                int off = key * 136 + s * 16 + 2 * t4;
                unsigned bh0 = *(const unsigned*)&Khi[off];
                unsigned bh1 = *(const unsigned*)&Khi[off + 8];
                unsigned bl0 = *(const unsigned*)&Klo[off];
                unsigned bl1 = *(const unsigned*)&Klo[off + 8];
                mma_bf16(sacc[nf], qhi[s], bh0, bh1);
                mma_bf16(sacc[nf], qhi[s], bl0, bl1);
                mma_bf16(sacc[nf], qlo[s], bh0, bh1);
            }
        }

        // ---- causal mask (only possible on the last two tiles) ----
        if (kb >= 2 * qb) {
            int colb = kb * 64 + 2 * t4;
#pragma unroll
            for (int nf = 0; nf < 8; nf++) {
                int c0 = colb + nf * 8, c1 = c0 + 1;
                if (c0 > rowg0) sacc[nf][0] = -INFINITY;
                if (c1 > rowg0) sacc[nf][1] = -INFINITY;
                if (c0 > rowg1) sacc[nf][2] = -INFINITY;
                if (c1 > rowg1) sacc[nf][3] = -INFINITY;
            }
        }

        // ---- online softmax (warp-local: rows fully owned) ----
        float mx0 = -INFINITY, mx1 = -INFINITY;
#pragma unroll
        for (int nf = 0; nf < 8; nf++) {
            mx0 = fmaxf(mx0, fmaxf(sacc[nf][0], sacc[nf][1]));
            mx1 = fmaxf(mx1, fmaxf(sacc[nf][2], sacc[nf][3]));
        }
        mx0 = fmaxf(mx0, __shfl_xor_sync(0xffffffffu, mx0, 1));
        mx0 = fmaxf(mx0, __shfl_xor_sync(0xffffffffu, mx0, 2));
        mx1 = fmaxf(mx1, __shfl_xor_sync(0xffffffffu, mx1, 1));
        mx1 = fmaxf(mx1, __shfl_xor_sync(0xffffffffu, mx1, 2));
        float mn0 = fmaxf(m0, mx0);
        float mn1 = fmaxf(m1, mx1);
        float al0 = __expf(m0 - mn0);
        float al1 = __expf(m1 - mn1);
        float su0 = 0.f, su1 = 0.f;
        int pr0 = (wrow + g4) * 72 + 2 * t4;
        int pr1 = (wrow + g4 + 8) * 72 + 2 * t4;
#pragma unroll
        for (int nf = 0; nf < 8; nf++) {
            float p00 = __expf(sacc[nf][0] - mn0);
            float p01 = __expf(sacc[nf][1] - mn0);
            float p10 = __expf(sacc[nf][2] - mn1);
            float p11 = __expf(sacc[nf][3] - mn1);
            su0 += p00 + p01;
            su1 += p10 + p11;
            *(float2*)&Ps[pr0 + nf * 8] = make_float2(
                __uint_as_float(tf32_of(p00)), __uint_as_float(tf32_of(p01)));
            *(float2*)&Ps[pr1 + nf * 8] = make_float2(
                __uint_as_float(tf32_of(p10)), __uint_as_float(tf32_of(p11)));
        }
        su0 += __shfl_xor_sync(0xffffffffu, su0, 1);
        su0 += __shfl_xor_sync(0xffffffffu, su0, 2);
        su1 += __shfl_xor_sync(0xffffffffu, su1, 1);
        su1 += __shfl_xor_sync(0xffffffffu, su1, 2);
        l0 = l0 * al0 + su0;
        l1 = l1 * al1 + su1;
        m0 = mn0;
        m1 = mn1;
#pragma unroll
        for (int nf = 0; nf < 16; nf++) {
            o[nf][0] *= al0; o[nf][1] *= al0;
            o[nf][2] *= al1; o[nf][3] *= al1;
        }
        __syncwarp();   // P written/read only within this warp

        // ---- O += P V  (1-pass tf32) ----
#pragma unroll
        for (int kk = 0; kk < 8; kk++) {
            int pa = (wrow + g4) * 72 + kk * 8 + t4;
            int pb = (wrow + g4 + 8) * 72 + kk * 8 + t4;
            unsigned a0 = __float_as_uint(Ps[pa]);
            unsigned a1 = __float_as_uint(Ps[pb]);
            unsigned a2 = __float_as_uint(Ps[pa + 4]);
            unsigned a3 = __float_as_uint(Ps[pb + 4]);
#pragma unroll
            for (int nf = 0; nf < 16; nf++) {
                unsigned b0 = __float_as_uint(Vs[(kk * 8 + t4) * 136 + nf * 8 + g4]);
                unsigned b1 = __float_as_uint(Vs[(kk * 8 + t4 + 4) * 136 + nf * 8 + g4]);
                mma_tf32(o[nf], a0, a1, a2, a3, b0, b1);
            }
        }
        __syncthreads();   // all warps done with K/V before next tile load
    }

    // ---- epilogue ----
    float inv0 = 1.0f / l0;
    float inv1 = 1.0f / l1;
    size_t t0 = (size_t)(b * SS + qb * 128 + wrow + g4) * QSZ + h * HD + 2 * t4;
    size_t t1 = t0 + 8 * QSZ;
#pragma unroll
    for (int nf = 0; nf < 16; nf++) {
        *(float2*)&attn[t0 + nf * 8] = make_float2(o[nf][0] * inv0, o[nf][1] * inv0);
        *(float2*)&attn[t1 + nf * 8] = make_float2(o[nf][2] * inv1, o[nf][3] * inv1);
    }
}

// ---------------------------------------------------------------------------
extern "C" void kernel_launch(void* const* d_in, const int* in_sizes, int n_in,
                              void* d_out, int out_size)
{
    (void)in_sizes; (void)n_in; (void)out_size;
    const float* hidden    = (const float*)d_in[0];
    const int*   positions = (const int*)d_in[1];
    const float* Wqkv      = (const float*)d_in[2];
    const float* bqkv      = (const float*)d_in[3];
    const float* Wo        = (const float*)d_in[4];
    float* out = (float*)d_out;

    float *qkv, *attn, *ct, *st;
    cudaGetSymbolAddress((void**)&qkv,  g_qkv);
    cudaGetSymbolAddress((void**)&attn, g_attn);
    cudaGetSymbolAddress((void**)&ct,   g_cos);
    cudaGetSymbolAddress((void**)&st,   g_sin);

    cudaFuncSetAttribute(flash_mma,
                         cudaFuncAttributeMaxDynamicSharedMemorySize, FL_SMEM);

    rope_table_kernel<<<SS, 64>>>(ct, st);

    dim3 g1(QKVSZ / 128, NT / 128);  // (36, 32)
    sgemm_tf32<<<g1, 256>>>(hidden, Wqkv, bqkv, qkv, NT, QKVSZ, HH);

    dim3 gr(NT, NH + NKV);
    rope_kernel<<<gr, 64>>>(qkv, positions, ct, st);

    dim3 gf(SS / 128, NH, BB);  // (16, 28, 2)
    flash_mma<<<gf, 256, FL_SMEM>>>(qkv, attn);

    dim3 g2(HH / 128, NT / 128);  // (28, 32)
    sgemm_tf32<<<g2, 256>>>(attn, Wo, nullptr, out, NT, HH, HH);
}